// round 16
// baseline (speedup 1.0000x reference)
#include <cuda_runtime.h>
#include <cuda_bf16.h>
#include <cstdint>

// Problem constants
#define HEADS   8
#define NTOK    49
#define CDIM    256
#define HD      32
#define BATCH   4096
#define NWIN    64
#define M_TOTAL (BATCH * NTOK)      // 200704
#define QKV_N   768

// ---------------------------------------------------------------------------
// Scratch (__device__ globals; allocation-free rule).
// g_q/g_k: [b*h][64][32] token-padded (rows 49..63 stay zero from BSS init).
// g_v: [b*h][32][64] = v^T, token-padded likewise.
// g_xr/g_y/weights: tf32-rounded, kperm2 layout (k-step-pair packed).
// ---------------------------------------------------------------------------
__device__ float g_xr[(size_t)M_TOTAL * CDIM];
__device__ float g_q[(size_t)BATCH * HEADS * 64 * HD];
__device__ float g_k[(size_t)BATCH * HEADS * 64 * HD];
__device__ float g_v[(size_t)BATCH * HEADS * HD * 64];
__device__ float g_y[(size_t)M_TOTAL * CDIM];
__device__ float g_wt_qkv[(size_t)QKV_N * CDIM];
__device__ float g_wt_proj[(size_t)CDIM * CDIM];
__device__ __nv_bfloat16 g_bm[(size_t)NWIN * HEADS * 64 * 56]; // bias+mask bf16

__device__ __forceinline__ float to_tf32(float x) {
    float r;
    asm("cvt.rna.tf32.f32 %0, %1;" : "=f"(r) : "f"(x));
    return r;
}
__device__ __forceinline__ uint32_t smem_u32(const void* p) {
    uint32_t a;
    asm("{ .reg .u64 t; cvta.to.shared.u64 t, %1; cvt.u32.u64 %0, t; }" : "=r"(a) : "l"(p));
    return a;
}
__device__ __forceinline__ void cp_async16(uint32_t saddr, const void* gaddr) {
    asm volatile("cp.async.cg.shared.global [%0], [%1], 16;" :: "r"(saddr), "l"(gaddr));
}
#define CP_COMMIT() asm volatile("cp.async.commit_group;" ::: "memory")
#define CP_WAIT0()  asm volatile("cp.async.wait_group 0;" ::: "memory")

#define MMA_TF32(acc, a0, a1, a2, a3, b0, b1) \
    asm volatile("mma.sync.aligned.m16n8k8.row.col.f32.tf32.tf32.f32 " \
        "{%0,%1,%2,%3}, {%4,%5,%6,%7}, {%8,%9}, {%0,%1,%2,%3};" \
        : "+f"((acc)[0]), "+f"((acc)[1]), "+f"((acc)[2]), "+f"((acc)[3]) \
        : "r"(a0), "r"(a1), "r"(a2), "r"(a3), "r"(b0), "r"(b1))

// kperm2: within each 32-col chunk, logical k = 16s + 8t + 4h + q
// -> phys 16s + 4q + 2t + h. Packs k-step pairs for LDS.128 fragment loads.
__device__ __host__ __forceinline__ int kperm2(int x) {
    return ((x >> 4) & 1) * 16 + (x & 3) * 4 + ((x >> 3) & 1) * 2 + ((x >> 2) & 1);
}

// ---------------------------------------------------------------------------
// Prepass: round x -> g_xr (tf32 rna), kperm2 layout.
// Per 16-float halfchunk: out[q] = {l[q], l[q+4], l[q+8], l[q+12]}
// = a 4x4 register transpose of four float4s. Fully vectorized both sides.
// ---------------------------------------------------------------------------
__global__ __launch_bounds__(256) void round_x_kernel(const float4* __restrict__ x) {
    size_t hc = (size_t)blockIdx.x * 256 + threadIdx.x;   // halfchunk (16 floats)
    const float4* src = x + hc * 4;
    float4* dst = (float4*)g_xr + hc * 4;
    float4 v[4];
    #pragma unroll
    for (int i = 0; i < 4; i++) {
        float4 t = src[i];
        v[i] = make_float4(to_tf32(t.x), to_tf32(t.y), to_tf32(t.z), to_tf32(t.w));
    }
    dst[0] = make_float4(v[0].x, v[1].x, v[2].x, v[3].x);
    dst[1] = make_float4(v[0].y, v[1].y, v[2].y, v[3].y);
    dst[2] = make_float4(v[0].z, v[1].z, v[2].z, v[3].z);
    dst[3] = make_float4(v[0].w, v[1].w, v[2].w, v[3].w);
}

// ---------------------------------------------------------------------------
// Weight transpose: W[K][N] -> Wt[N][kperm2(K)], tf32-rounded
// ---------------------------------------------------------------------------
__global__ void transpose_kernel(const float* __restrict__ W, int K, int N, int sel) {
    float* Wt = sel ? g_wt_proj : g_wt_qkv;
    __shared__ float t[32][33];
    int bn = blockIdx.x * 32, bk = blockIdx.y * 32;
    int x = threadIdx.x, y = threadIdx.y;
    #pragma unroll
    for (int i = 0; i < 32; i += 8)
        t[y + i][x] = W[(size_t)(bk + y + i) * N + bn + x];
    __syncthreads();
    #pragma unroll
    for (int i = 0; i < 32; i += 8)
        Wt[(size_t)(bn + y + i) * K + bk + kperm2(x)] = to_tf32(t[x][y + i]);
}

// ---------------------------------------------------------------------------
// bias+mask precompute -> bf16, rows padded to 64, cols to 56 (-30 pad)
// ---------------------------------------------------------------------------
__global__ void bm_kernel(const float* __restrict__ bias_table,
                          const float* __restrict__ mask,
                          const int*   __restrict__ rel_idx) {
    const int w = blockIdx.x >> 3, h = blockIdx.x & 7;
    __nv_bfloat16* dst = g_bm + (size_t)blockIdx.x * (64 * 56);
    for (int t = threadIdx.x; t < 64 * 56; t += 256) {
        int i = t / 56, j = t - i * 56;
        float v = -30.0f;
        if (i < NTOK && j < NTOK)
            v = bias_table[rel_idx[i * NTOK + j] * HEADS + h]
              + mask[((size_t)w * NTOK + i) * NTOK + j];
        dst[t] = __float2bfloat16(v);
    }
}

// ---------------------------------------------------------------------------
// tf32 mma.sync GEMM: BM=128,BN=128,BK=32, 8 warps (2x4), warp tile 64x32.
// cp.async 2-stage, one __syncthreads per chunk. kperm2 globals ->
// LDS.128 fragment gathers (24/warp/chunk). Pitch 48: 16B-unit stride
// 12 ≡ 4 (mod 8) -> conflict-free quarter-warp phases for LDS.128.
// smem: 2 stages x (A[128][48] + B[128][48]) = 96 KB -> 2 CTAs/SM.
// ---------------------------------------------------------------------------
#define GP 48
#define STAGE_F 6144                 // floats per tile (128*48)
#define STAGE_B 24576                // bytes per tile
#define SMTOT_BYTES (2 * 2 * STAGE_B) // 98304

template <int EPI>
__global__ __launch_bounds__(256, 2) void tc_gemm(const float* __restrict__ bias,
                                                  float* __restrict__ Cout) {
    extern __shared__ float sm[];
    const uint32_t sbase = smem_u32(sm);
    const float* A  = (EPI == 1) ? (const float*)g_y : (const float*)g_xr;
    const float* Bt = (EPI == 1) ? (const float*)g_wt_proj : (const float*)g_wt_qkv;

    const int tid = threadIdx.x;
    const int wid = tid >> 5, lid = tid & 31;
    const int wm = wid >> 2, wn = wid & 3;       // warp grid 2 x 4, tile 64 x 32
    const int g = lid >> 2, q = lid & 3;
    const int cRow = blockIdx.y, cCol = blockIdx.x;

    // staging coordinates: 32 rows per iter, 8 float4 per row
    const int f0row = tid >> 3;            // 0..31 (+ it*32)
    const int f0col = (tid & 7) * 4;       // 0,4,..,28
    const float* Ap = A  + (size_t)(cRow * 128 + f0row) * CDIM + f0col;
    const float* Bp = Bt + (size_t)(cCol * 128 + f0row) * CDIM + f0col;
    const uint32_t soff = (uint32_t)(f0row * GP + f0col) * 4;

    #define ISSUE_STAGE(c, s) do { \
        uint32_t _sa = sbase + (uint32_t)(s) * (2 * STAGE_B) + soff; \
        uint32_t _sb = _sa + STAGE_B; \
        const float* _ap = Ap + (c) * 32; \
        const float* _bp = Bp + (c) * 32; \
        _Pragma("unroll") \
        for (int _it = 0; _it < 4; _it++) { \
            cp_async16(_sa + _it * (32 * GP * 4), _ap + (size_t)_it * 32 * CDIM); \
            cp_async16(_sb + _it * (32 * GP * 4), _bp + (size_t)_it * 32 * CDIM); \
        } \
        CP_COMMIT(); \
    } while (0)

    ISSUE_STAGE(0, 0);

    float acc[4][4][4];
    #pragma unroll
    for (int i = 0; i < 4; i++)
        #pragma unroll
        for (int j = 0; j < 4; j++)
            #pragma unroll
            for (int r = 0; r < 4; r++) acc[i][j][r] = 0.0f;

    #pragma unroll 1
    for (int c = 0; c < 8; c++) {
        CP_WAIT0();           // own chunk-c copies arrived
        __syncthreads();      // everyone's arrived; everyone done with chunk c-1
        if (c < 7) ISSUE_STAGE(c + 1, (c + 1) & 1);   // overlaps chunk-c mma

        const float* as = sm + (c & 1) * (2 * STAGE_F);
        const float* bs = as + STAGE_F;

        #pragma unroll
        for (int p = 0; p < 2; p++) {          // k-step pairs (2p, 2p+1)
            const int kc = p * 16 + 4 * q;
            float4 bb[4];
            #pragma unroll
            for (int j = 0; j < 4; j++)
                bb[j] = *(const float4*)(bs + (wn * 32 + j * 8 + g) * GP + kc);
            #pragma unroll
            for (int i = 0; i < 4; i++) {
                const float* ap = as + (wm * 64 + i * 16 + g) * GP + kc;
                float4 aA = *(const float4*)ap;             // a0,a2 (2p) | a0,a2 (2p+1)
                float4 aB = *(const float4*)(ap + 8 * GP);  // a1,a3 (2p) | a1,a3 (2p+1)
                #pragma unroll
                for (int j = 0; j < 4; j++) {
                    MMA_TF32(acc[i][j],
                             __float_as_uint(aA.x), __float_as_uint(aB.x),
                             __float_as_uint(aA.y), __float_as_uint(aB.y),
                             __float_as_uint(bb[j].x), __float_as_uint(bb[j].y));
                    MMA_TF32(acc[i][j],
                             __float_as_uint(aA.z), __float_as_uint(aB.z),
                             __float_as_uint(aA.w), __float_as_uint(aB.w),
                             __float_as_uint(bb[j].z), __float_as_uint(bb[j].w));
                }
            }
        }
    }

    // ------------------- epilogue -------------------
    const int nbase = cCol * 128 + wn * 32;   // 32-aligned: single (t,h) per warp
    float bv[4][2];
    #pragma unroll
    for (int j = 0; j < 4; j++) {
        int n = nbase + j * 8 + 2 * q;
        bv[j][0] = __ldg(bias + n);
        bv[j][1] = __ldg(bias + n + 1);
    }

    if (EPI == 0) {
        const int t = nbase >> 8;
        const int h = (nbase >> 5) & 7;
        if (t < 2) {
            // q / k: [b*h][64][32] token-padded layout
            const float sc = (t == 0) ? 0.17677669529663687f : 1.0f;
            float* gdst = (t == 0) ? g_q : g_k;
            #pragma unroll
            for (int i = 0; i < 4; i++) {
                #pragma unroll
                for (int rr = 0; rr < 2; rr++) {
                    int m = cRow * 128 + wm * 64 + i * 16 + g + rr * 8;
                    int bwin = m / NTOK;
                    int nn = m - bwin * NTOK;
                    float* dst = gdst + (((size_t)(bwin * HEADS + h) * 64 + nn) * HD);
                    #pragma unroll
                    for (int j = 0; j < 4; j++) {
                        float2 o;
                        o.x = (acc[i][j][rr * 2 + 0] + bv[j][0]) * sc;
                        o.y = (acc[i][j][rr * 2 + 1] + bv[j][1]) * sc;
                        *(float2*)(dst + j * 8 + 2 * q) = o;
                    }
                }
            }
        } else {
            // v: transposed [b*h][32][64] token-padded layout
            #pragma unroll
            for (int i = 0; i < 4; i++) {
                #pragma unroll
                for (int rr = 0; rr < 2; rr++) {
                    int m = cRow * 128 + wm * 64 + i * 16 + g + rr * 8;
                    int bwin = m / NTOK;
                    int nn = m - bwin * NTOK;
                    float* dstb = g_v + (size_t)(bwin * HEADS + h) * (HD * 64) + nn;
                    #pragma unroll
                    for (int j = 0; j < 4; j++) {
                        int d = j * 8 + 2 * q;
                        dstb[(size_t)d * 64]       = acc[i][j][rr * 2 + 0] + bv[j][0];
                        dstb[(size_t)(d + 1) * 64] = acc[i][j][rr * 2 + 1] + bv[j][1];
                    }
                }
            }
        }
    } else {
        #pragma unroll
        for (int i = 0; i < 4; i++) {
            #pragma unroll
            for (int rr = 0; rr < 2; rr++) {
                int m = cRow * 128 + wm * 64 + i * 16 + g + rr * 8;
                float* dst = Cout + (size_t)m * CDIM + nbase;
                #pragma unroll
                for (int j = 0; j < 4; j++) {
                    float2 o;
                    o.x = acc[i][j][rr * 2 + 0] + bv[j][0];
                    o.y = acc[i][j][rr * 2 + 1] + bv[j][1];
                    *(float2*)(dst + j * 8 + 2 * q) = o;
                }
            }
        }
    }
}

// ---------------------------------------------------------------------------
// MMA flash attention: 64 threads per (window, head). All staging via
// cp.async from padded globals. BM prefetched to regs while copies fly.
// Output to g_y tf32-rounded + kperm2 (proj's cp.async consumes it).
// smem: Q[64][36] | K[56][36] | Vt[32][68]; P[64][60] aliases Q+K region.
// ---------------------------------------------------------------------------
#define PITCH 36
#define VP 68
#define KS_OFF  2304
#define VTS_OFF 4320
#define SM_FLOATS (VTS_OFF + 32 * VP)   // 6496

__global__ __launch_bounds__(64) void attn_mma_kernel() {
    __shared__ float sm[SM_FLOATS];
    float* Qs  = sm;             // [64][36]
    float* Ks  = sm + KS_OFF;    // [56][36]
    float* Vts = sm + VTS_OFF;   // [32][68]
    float* Ps  = sm;             // [64][60] aliases Q+K after sync (3840 <= 4320)

    const int blk = blockIdx.x;          // b*8 + h
    const int b = blk >> 3, h = blk & 7;
    const int tid = threadIdx.x, wid = tid >> 5, lid = tid & 31;
    const int g = lid >> 2, q = lid & 3;
    const int rbase = wid * 32;

    const float* qg = g_q + (size_t)blk * 2048;   // [64][32]
    const float* kg = g_k + (size_t)blk * 2048;   // [64][32]
    const float* vg = g_v + (size_t)blk * 2048;   // [32][64]
    const uint32_t sq = smem_u32(Qs), sk = smem_u32(Ks), sv = smem_u32(Vts);

    // ---- stage Q (64 rows), K (56 rows), V^T (32 rows x 64) via cp.async ----
    #pragma unroll
    for (int it = 0; it < 8; it++) {
        int c16 = tid + it * 64;
        int row = c16 >> 3, col = c16 & 7;
        cp_async16(sq + (uint32_t)(row * PITCH + col * 4) * 4, qg + row * 32 + col * 4);
    }
    #pragma unroll
    for (int it = 0; it < 7; it++) {
        int c16 = tid + it * 64;
        int row = c16 >> 3, col = c16 & 7;
        cp_async16(sk + (uint32_t)(row * PITCH + col * 4) * 4, kg + row * 32 + col * 4);
    }
    #pragma unroll
    for (int it = 0; it < 8; it++) {
        int c16 = tid + it * 64;
        int row = c16 >> 4, col = c16 & 15;
        cp_async16(sv + (uint32_t)(row * VP + col * 4) * 4, vg + row * 64 + col * 4);
    }
    CP_COMMIT();

    // ---- prefetch bias+mask (bf16x2) while copies fly ----
    const __nv_bfloat16* bmg = g_bm + ((size_t)((b & (NWIN - 1)) * HEADS + h)) * (64 * 56);
    uint32_t bmr[2][2][7];
    #pragma unroll
    for (int mi = 0; mi < 2; mi++) {
        const int r0 = rbase + mi * 16 + g;
        #pragma unroll
        for (int nj = 0; nj < 7; nj++) {
            const int cc = nj * 8 + 2 * q;
            bmr[mi][0][nj] = *(const uint32_t*)(bmg + r0 * 56 + cc);
            bmr[mi][1][nj] = *(const uint32_t*)(bmg + (r0 + 8) * 56 + cc);
        }
    }

    CP_WAIT0();
    __syncthreads();

    // ---- QK^T ----
    float s[2][7][4];
    #pragma unroll
    for (int mi = 0; mi < 2; mi++)
        #pragma unroll
        for (int nj = 0; nj < 7; nj++)
            #pragma unroll
            for (int r = 0; r < 4; r++) s[mi][nj][r] = 0.0f;

    #pragma unroll
    for (int ks = 0; ks < 4; ks++) {
        const int kc = ks * 8 + q;
        uint32_t b0[7], b1[7];
        #pragma unroll
        for (int nj = 0; nj < 7; nj++) {
            const float* bp = Ks + (nj * 8 + g) * PITCH + kc;
            b0[nj] = __float_as_uint(bp[0]);
            b1[nj] = __float_as_uint(bp[4]);
        }
        #pragma unroll
        for (int mi = 0; mi < 2; mi++) {
            const float* ap = Qs + (rbase + mi * 16 + g) * PITCH + kc;
            uint32_t a0 = __float_as_uint(ap[0]);
            uint32_t a2 = __float_as_uint(ap[4]);
            uint32_t a1 = __float_as_uint(ap[8 * PITCH]);
            uint32_t a3 = __float_as_uint(ap[8 * PITCH + 4]);
            #pragma unroll
            for (int nj = 0; nj < 7; nj++)
                MMA_TF32(s[mi][nj], a0, a1, a2, a3, b0[nj], b1[nj]);
        }
    }

    // ---- softmax ----
    float inv[2][2];
    #pragma unroll
    for (int mi = 0; mi < 2; mi++) {
        float l0 = 0.0f, l1 = 0.0f;
        #pragma unroll
        for (int nj = 0; nj < 7; nj++) {
            float2 bmA = __bfloat1622float2(*(__nv_bfloat162*)&bmr[mi][0][nj]);
            float2 bmB = __bfloat1622float2(*(__nv_bfloat162*)&bmr[mi][1][nj]);
            float e0 = __expf(s[mi][nj][0] + bmA.x);
            float e1 = __expf(s[mi][nj][1] + bmA.y);
            float e2 = __expf(s[mi][nj][2] + bmB.x);
            float e3 = __expf(s[mi][nj][3] + bmB.y);
            s[mi][nj][0] = e0; s[mi][nj][1] = e1;
            s[mi][nj][2] = e2; s[mi][nj][3] = e3;
            l0 += e0 + e1;
            l1 += e2 + e3;
        }
        l0 += __shfl_xor_sync(0xffffffffu, l0, 1);
        l0 += __shfl_xor_sync(0xffffffffu, l0, 2);
        l1 += __shfl_xor_sync(0xffffffffu, l1, 1);
        l1 += __shfl_xor_sync(0xffffffffu, l1, 2);
        inv[mi][0] = 1.0f / l0;
        inv[mi][1] = 1.0f / l1;
    }

    __syncthreads();   // both warps done reading Qs/Ks before P overwrites

    // ---- stage P ----
    #pragma unroll
    for (int mi = 0; mi < 2; mi++) {
        const int r0 = rbase + mi * 16 + g;
        #pragma unroll
        for (int nj = 0; nj < 7; nj++) {
            const int cc = nj * 8 + 2 * q;
            *(float2*)(Ps + r0 * 60 + cc)       = make_float2(s[mi][nj][0], s[mi][nj][1]);
            *(float2*)(Ps + (r0 + 8) * 60 + cc) = make_float2(s[mi][nj][2], s[mi][nj][3]);
        }
    }
    __syncwarp();

    // ---- P x V ----
    float o[2][4][4];
    #pragma unroll
    for (int mi = 0; mi < 2; mi++)
        #pragma unroll
        for (int nj = 0; nj < 4; nj++)
            #pragma unroll
            for (int r = 0; r < 4; r++) o[mi][nj][r] = 0.0f;

    #pragma unroll
    for (int ks = 0; ks < 7; ks++) {
        const int kc = ks * 8 + q;
        uint32_t b0[4], b1[4];
        #pragma unroll
        for (int nj = 0; nj < 4; nj++) {
            const float* bp = Vts + (nj * 8 + g) * VP + kc;
            b0[nj] = __float_as_uint(bp[0]);
            b1[nj] = __float_as_uint(bp[4]);
        }
        #pragma unroll
        for (int mi = 0; mi < 2; mi++) {
            const float* ap = Ps + (rbase + mi * 16 + g) * 60 + kc;
            uint32_t a0 = __float_as_uint(ap[0]);
            uint32_t a2 = __float_as_uint(ap[4]);
            uint32_t a1 = __float_as_uint(ap[8 * 60]);
            uint32_t a3 = __float_as_uint(ap[8 * 60 + 4]);
            #pragma unroll
            for (int nj = 0; nj < 4; nj++)
                MMA_TF32(o[mi][nj], a0, a1, a2, a3, b0[nj], b1[nj]);
        }
    }

    // ---- normalize + store to g_y (tf32-rounded, kperm2) ----
    // logical col d0 = nj*8 + 2q -> phys 16(nj>>1) + 2(nj&1) + 8(q&1) + (q>>1);
    // d0+1 -> phys + 4.
    const int p0 = 8 * (q & 1) + (q >> 1);
    #pragma unroll
    for (int mi = 0; mi < 2; mi++) {
        #pragma unroll
        for (int rr = 0; rr < 2; rr++) {
            const int row = rbase + mi * 16 + g + rr * 8;
            if (row < NTOK) {
                const float iv = inv[mi][rr];
                float* dst = g_y + ((size_t)b * NTOK + row) * CDIM + h * HD;
                #pragma unroll
                for (int nj = 0; nj < 4; nj++) {
                    const int ph = 16 * (nj >> 1) + 2 * (nj & 1) + p0;
                    dst[ph]     = to_tf32(o[mi][nj][rr * 2 + 0] * iv);
                    dst[ph + 4] = to_tf32(o[mi][nj][rr * 2 + 1] * iv);
                }
            }
        }
    }
}

// ---------------------------------------------------------------------------
// Launch
// ---------------------------------------------------------------------------
extern "C" void kernel_launch(void* const* d_in, const int* in_sizes, int n_in,
                              void* d_out, int out_size)
{
    const float* x          = (const float*)d_in[0];
    const float* mask       = (const float*)d_in[1];
    const float* qkv_w      = (const float*)d_in[2];
    const float* qkv_b      = (const float*)d_in[3];
    const float* bias_table = (const float*)d_in[4];
    const float* proj_w     = (const float*)d_in[5];
    const float* proj_b     = (const float*)d_in[6];
    const int*   rel_idx    = (const int*)d_in[7];
    float* out = (float*)d_out;

    cudaFuncSetAttribute(tc_gemm<0>, cudaFuncAttributeMaxDynamicSharedMemorySize, SMTOT_BYTES);
    cudaFuncSetAttribute(tc_gemm<1>, cudaFuncAttributeMaxDynamicSharedMemorySize, SMTOT_BYTES);

    // 0) prepass: round+permute x; weight transposes (kperm2); bf16 bias+mask
    round_x_kernel<<<M_TOTAL * CDIM / 4096, 256>>>((const float4*)x);
    transpose_kernel<<<dim3(QKV_N / 32, CDIM / 32), dim3(32, 8)>>>(qkv_w, CDIM, QKV_N, 0);
    transpose_kernel<<<dim3(CDIM / 32, CDIM / 32), dim3(32, 8)>>>(proj_w, CDIM, CDIM, 1);
    bm_kernel<<<NWIN * HEADS, 256>>>(bias_table, mask, rel_idx);

    // 1) QKV: g_xr [200704 x 256] x [256 x 768] -> g_q/g_k/g_v (padded/transposed)
    tc_gemm<0><<<dim3(QKV_N / 128, M_TOTAL / 128), 256, SMTOT_BYTES>>>(qkv_b, nullptr);

    // 2) attention -> g_y (tf32-rounded, kperm2)
    attn_mma_kernel<<<BATCH * HEADS, 64>>>();

    // 3) proj: g_y x [256 x 256] -> out
    tc_gemm<1><<<dim3(CDIM / 128, M_TOTAL / 128), 256, SMTOT_BYTES>>>(proj_b, out);
}

// round 17
// speedup vs baseline: 1.0767x; 1.0767x over previous
#include <cuda_runtime.h>
#include <cuda_bf16.h>
#include <cstdint>

// Problem constants
#define HEADS   8
#define NTOK    49
#define CDIM    256
#define HD      32
#define BATCH   4096
#define NWIN    64
#define M_TOTAL (BATCH * NTOK)      // 200704
#define QKV_N   768

// ---------------------------------------------------------------------------
// Scratch (__device__ globals; allocation-free rule).
// g_q/g_k: [b*h][64][32] token-padded (rows 49..63 stay zero from BSS init).
// g_v: [b*h][32][64] = v^T, token-padded likewise.
// g_xr/g_y/weights: tf32-rounded, k-permuted (kperm) layout.
// ---------------------------------------------------------------------------
__device__ float g_xr[(size_t)M_TOTAL * CDIM];
__device__ float g_q[(size_t)BATCH * HEADS * 64 * HD];
__device__ float g_k[(size_t)BATCH * HEADS * 64 * HD];
__device__ float g_v[(size_t)BATCH * HEADS * HD * 64];
__device__ float g_y[(size_t)M_TOTAL * CDIM];
__device__ float g_wt_qkv[(size_t)QKV_N * CDIM];
__device__ float g_wt_proj[(size_t)CDIM * CDIM];
__device__ __nv_bfloat16 g_bm[(size_t)NWIN * HEADS * 64 * 56]; // bias+mask bf16

__device__ __forceinline__ float to_tf32(float x) {
    float r;
    asm("cvt.rna.tf32.f32 %0, %1;" : "=f"(r) : "f"(x));
    return r;
}
__device__ __forceinline__ uint32_t smem_u32(const void* p) {
    uint32_t a;
    asm("{ .reg .u64 t; cvta.to.shared.u64 t, %1; cvt.u32.u64 %0, t; }" : "=r"(a) : "l"(p));
    return a;
}
__device__ __forceinline__ void cp_async16(uint32_t saddr, const void* gaddr) {
    asm volatile("cp.async.cg.shared.global [%0], [%1], 16;" :: "r"(saddr), "l"(gaddr));
}
#define CP_COMMIT() asm volatile("cp.async.commit_group;" ::: "memory")
#define CP_WAIT0()  asm volatile("cp.async.wait_group 0;" ::: "memory")

#define MMA_TF32(acc, a0, a1, a2, a3, b0, b1) \
    asm volatile("mma.sync.aligned.m16n8k8.row.col.f32.tf32.tf32.f32 " \
        "{%0,%1,%2,%3}, {%4,%5,%6,%7}, {%8,%9}, {%0,%1,%2,%3};" \
        : "+f"((acc)[0]), "+f"((acc)[1]), "+f"((acc)[2]), "+f"((acc)[3]) \
        : "r"(a0), "r"(a1), "r"(a2), "r"(a3), "r"(b0), "r"(b1))

// k-permutation within each 32-col chunk: logical k=8s+q+4h -> phys 8s+2q+h
__device__ __host__ __forceinline__ int kperm(int x) {
    return (x & 24) + ((x & 3) << 1) + ((x >> 2) & 1);
}

// ---------------------------------------------------------------------------
// Fused prepass kernel: ONE launch, partitioned grid (small tasks first so
// they are not tail-delayed behind round_x's streaming blocks).
//   blocks [0, 512)       : bm  (bias+mask -> bf16, 64x56 padded)
//   blocks [512, 704)     : transpose qkv_w -> g_wt_qkv  (24 x 8 tiles)
//   blocks [704, 768)     : transpose proj_w -> g_wt_proj (8 x 8 tiles)
//   blocks [768, 13312)   : round x -> g_xr (tf32 rna, kperm layout)
// ---------------------------------------------------------------------------
#define NB_BM  512
#define NB_T1  192
#define NB_T2  64
#define NB_RX  (M_TOTAL * CDIM / 4096)          // 12544
#define NB_PREP (NB_BM + NB_T1 + NB_T2 + NB_RX) // 13312

__global__ __launch_bounds__(256) void prep_kernel(
    const float* __restrict__ x,
    const float* __restrict__ qkv_w,
    const float* __restrict__ proj_w,
    const float* __restrict__ bias_table,
    const float* __restrict__ mask,
    const int*   __restrict__ rel_idx)
{
    __shared__ float t[32][33];
    const int bid = blockIdx.x;
    const int tid = threadIdx.x;

    if (bid < NB_BM) {
        // ---- bias+mask precompute ----
        const int w = bid >> 3, h = bid & 7;
        __nv_bfloat16* dst = g_bm + (size_t)bid * (64 * 56);
        for (int tt = tid; tt < 64 * 56; tt += 256) {
            int i = tt / 56, j = tt - i * 56;
            float v = -30.0f;
            if (i < NTOK && j < NTOK)
                v = bias_table[rel_idx[i * NTOK + j] * HEADS + h]
                  + mask[((size_t)w * NTOK + i) * NTOK + j];
            dst[tt] = __float2bfloat16(v);
        }
    } else if (bid < NB_BM + NB_T1 + NB_T2) {
        // ---- weight transpose: W[K][N] -> Wt[N][kperm(K)], tf32 ----
        const int local = bid - NB_BM;
        const bool is_qkv = (local < NB_T1);
        const int l2 = is_qkv ? local : (local - NB_T1);
        const int N = is_qkv ? QKV_N : CDIM;
        const int nbx = N / 32;
        const float* W = is_qkv ? qkv_w : proj_w;
        float* Wt = is_qkv ? g_wt_qkv : g_wt_proj;
        const int bn = (l2 % nbx) * 32, bk = (l2 / nbx) * 32;
        const int xx = tid & 31, yy = tid >> 5;   // (32, 8)
        #pragma unroll
        for (int i = 0; i < 32; i += 8)
            t[yy + i][xx] = W[(size_t)(bk + yy + i) * N + bn + xx];
        __syncthreads();
        #pragma unroll
        for (int i = 0; i < 32; i += 8)
            Wt[(size_t)(bn + yy + i) * CDIM + bk + kperm(xx)] = to_tf32(t[xx][yy + i]);
    } else {
        // ---- round + permute x -> g_xr ----
        const int rb = bid - (NB_BM + NB_T1 + NB_T2);
        size_t i = (size_t)rb * 1024 + tid;        // float4 slot index
        float4* dst = (float4*)g_xr;
        #pragma unroll
        for (int it = 0; it < 4; it++, i += 256) {
            size_t row = i >> 6;            // 64 float4 per row
            int v = (int)(i & 63);          // float4 slot in row
            int chunk = v >> 3, w = v & 7;  // 32-col chunk, slot within chunk
            const float* p = x + row * CDIM + chunk * 32 + (w >> 1) * 8 + (w & 1) * 2;
            float2 lo = *(const float2*)p;         // logical k0, k0+1
            float2 hi = *(const float2*)(p + 4);   // logical k0+4, k0+5
            dst[i] = make_float4(to_tf32(lo.x), to_tf32(hi.x), to_tf32(lo.y), to_tf32(hi.y));
        }
    }
}

// ---------------------------------------------------------------------------
// tf32 mma.sync GEMM (exact R14 core): BM=128,BN=128,BK=32, 8 warps (2x4),
// warp tile 64x32. cp.async 2-stage, one __syncthreads per chunk.
// k-permuted globals -> LDS.64 fragment gathers (pitch 40, conflict-free).
// smem: 2 stages x (A[128][40] + B[128][40]) = 80 KB -> 2 CTAs/SM.
// ---------------------------------------------------------------------------
#define GP 40
#define STAGE_F 5120                 // floats per tile (128*40)
#define STAGE_B 20480                // bytes per tile
#define SMTOT_BYTES (2 * 2 * STAGE_B) // 81920

template <int EPI>
__global__ __launch_bounds__(256, 2) void tc_gemm(const float* __restrict__ bias,
                                                  float* __restrict__ Cout) {
    extern __shared__ float sm[];
    const uint32_t sbase = smem_u32(sm);
    const float* A  = (EPI == 1) ? (const float*)g_y : (const float*)g_xr;
    const float* Bt = (EPI == 1) ? (const float*)g_wt_proj : (const float*)g_wt_qkv;

    const int tid = threadIdx.x;
    const int wid = tid >> 5, lid = tid & 31;
    const int wm = wid >> 2, wn = wid & 3;       // warp grid 2 x 4, tile 64 x 32
    const int g = lid >> 2, q = lid & 3;
    const int cRow = blockIdx.y, cCol = blockIdx.x;

    // staging coordinates: 32 rows per iter, 8 float4 per row
    const int f0row = tid >> 3;            // 0..31 (+ it*32)
    const int f0col = (tid & 7) * 4;       // 0,4,..,28
    const float* Ap = A  + (size_t)(cRow * 128 + f0row) * CDIM + f0col;
    const float* Bp = Bt + (size_t)(cCol * 128 + f0row) * CDIM + f0col;
    const uint32_t soff = (uint32_t)(f0row * GP + f0col) * 4;

    #define ISSUE_STAGE(c, s) do { \
        uint32_t _sa = sbase + (uint32_t)(s) * (2 * STAGE_B) + soff; \
        uint32_t _sb = _sa + STAGE_B; \
        const float* _ap = Ap + (c) * 32; \
        const float* _bp = Bp + (c) * 32; \
        _Pragma("unroll") \
        for (int _it = 0; _it < 4; _it++) { \
            cp_async16(_sa + _it * (32 * GP * 4), _ap + (size_t)_it * 32 * CDIM); \
            cp_async16(_sb + _it * (32 * GP * 4), _bp + (size_t)_it * 32 * CDIM); \
        } \
        CP_COMMIT(); \
    } while (0)

    ISSUE_STAGE(0, 0);

    float acc[4][4][4];
    #pragma unroll
    for (int i = 0; i < 4; i++)
        #pragma unroll
        for (int j = 0; j < 4; j++)
            #pragma unroll
            for (int r = 0; r < 4; r++) acc[i][j][r] = 0.0f;

    #pragma unroll 1
    for (int c = 0; c < 8; c++) {
        CP_WAIT0();           // own chunk-c copies arrived
        __syncthreads();      // everyone's arrived; everyone done with chunk c-1
        if (c < 7) ISSUE_STAGE(c + 1, (c + 1) & 1);   // overlaps chunk-c mma

        const float* as = sm + (c & 1) * (2 * STAGE_F);
        const float* bs = as + STAGE_F;

        #pragma unroll
        for (int ks = 0; ks < 4; ks++) {
            const int kc = ks * 8 + 2 * q;
            float2 bb[4];
            #pragma unroll
            for (int j = 0; j < 4; j++)
                bb[j] = *(const float2*)(bs + (wn * 32 + j * 8 + g) * GP + kc);
            #pragma unroll
            for (int i = 0; i < 4; i++) {
                const float* ap = as + (wm * 64 + i * 16 + g) * GP + kc;
                float2 aA = *(const float2*)ap;             // a0, a2
                float2 aB = *(const float2*)(ap + 8 * GP);  // a1, a3
                uint32_t a0 = __float_as_uint(aA.x), a2 = __float_as_uint(aA.y);
                uint32_t a1 = __float_as_uint(aB.x), a3 = __float_as_uint(aB.y);
                #pragma unroll
                for (int j = 0; j < 4; j++)
                    MMA_TF32(acc[i][j], a0, a1, a2, a3,
                             __float_as_uint(bb[j].x), __float_as_uint(bb[j].y));
            }
        }
    }

    // ------------------- epilogue -------------------
    const int nbase = cCol * 128 + wn * 32;   // 32-aligned: single (t,h) per warp
    float bv[4][2];
    #pragma unroll
    for (int j = 0; j < 4; j++) {
        int n = nbase + j * 8 + 2 * q;
        bv[j][0] = __ldg(bias + n);
        bv[j][1] = __ldg(bias + n + 1);
    }

    if (EPI == 0) {
        const int t = nbase >> 8;
        const int h = (nbase >> 5) & 7;
        if (t < 2) {
            // q / k: [b*h][64][32] token-padded layout
            const float sc = (t == 0) ? 0.17677669529663687f : 1.0f;
            float* gdst = (t == 0) ? g_q : g_k;
            #pragma unroll
            for (int i = 0; i < 4; i++) {
                #pragma unroll
                for (int rr = 0; rr < 2; rr++) {
                    int m = cRow * 128 + wm * 64 + i * 16 + g + rr * 8;
                    int bwin = m / NTOK;
                    int nn = m - bwin * NTOK;
                    float* dst = gdst + (((size_t)(bwin * HEADS + h) * 64 + nn) * HD);
                    #pragma unroll
                    for (int j = 0; j < 4; j++) {
                        float2 o;
                        o.x = (acc[i][j][rr * 2 + 0] + bv[j][0]) * sc;
                        o.y = (acc[i][j][rr * 2 + 1] + bv[j][1]) * sc;
                        *(float2*)(dst + j * 8 + 2 * q) = o;
                    }
                }
            }
        } else {
            // v: transposed [b*h][32][64] token-padded layout
            #pragma unroll
            for (int i = 0; i < 4; i++) {
                #pragma unroll
                for (int rr = 0; rr < 2; rr++) {
                    int m = cRow * 128 + wm * 64 + i * 16 + g + rr * 8;
                    int bwin = m / NTOK;
                    int nn = m - bwin * NTOK;
                    float* dstb = g_v + (size_t)(bwin * HEADS + h) * (HD * 64) + nn;
                    #pragma unroll
                    for (int j = 0; j < 4; j++) {
                        int d = j * 8 + 2 * q;
                        dstb[(size_t)d * 64]       = acc[i][j][rr * 2 + 0] + bv[j][0];
                        dstb[(size_t)(d + 1) * 64] = acc[i][j][rr * 2 + 1] + bv[j][1];
                    }
                }
            }
        }
    } else {
        #pragma unroll
        for (int i = 0; i < 4; i++) {
            #pragma unroll
            for (int rr = 0; rr < 2; rr++) {
                int m = cRow * 128 + wm * 64 + i * 16 + g + rr * 8;
                float* dst = Cout + (size_t)m * CDIM + nbase;
                #pragma unroll
                for (int j = 0; j < 4; j++) {
                    float2 o;
                    o.x = acc[i][j][rr * 2 + 0] + bv[j][0];
                    o.y = acc[i][j][rr * 2 + 1] + bv[j][1];
                    *(float2*)(dst + j * 8 + 2 * q) = o;
                }
            }
        }
    }
}

// ---------------------------------------------------------------------------
// MMA flash attention (exact R14): 64 threads per (window, head). All staging
// via cp.async from padded globals. BM prefetched to regs while copies fly.
// Output to g_y tf32-rounded + kperm (proj's cp.async consumes it).
// smem: Q[64][36] | K[56][36] | Vt[32][68]; P[64][60] aliases Q+K region.
// ---------------------------------------------------------------------------
#define PITCH 36
#define VP 68
#define KS_OFF  2304
#define VTS_OFF 4320
#define SM_FLOATS (VTS_OFF + 32 * VP)   // 6496

__global__ __launch_bounds__(64) void attn_mma_kernel() {
    __shared__ float sm[SM_FLOATS];
    float* Qs  = sm;             // [64][36]
    float* Ks  = sm + KS_OFF;    // [56][36]
    float* Vts = sm + VTS_OFF;   // [32][68]
    float* Ps  = sm;             // [64][60] aliases Q+K after sync (3840 <= 4320)

    const int blk = blockIdx.x;          // b*8 + h
    const int b = blk >> 3, h = blk & 7;
    const int tid = threadIdx.x, wid = tid >> 5, lid = tid & 31;
    const int g = lid >> 2, q = lid & 3;
    const int rbase = wid * 32;

    const float* qg = g_q + (size_t)blk * 2048;   // [64][32]
    const float* kg = g_k + (size_t)blk * 2048;   // [64][32]
    const float* vg = g_v + (size_t)blk * 2048;   // [32][64]
    const uint32_t sq = smem_u32(Qs), sk = smem_u32(Ks), sv = smem_u32(Vts);

    // ---- stage Q (64 rows), K (56 rows), V^T (32 rows x 64) via cp.async ----
    #pragma unroll
    for (int it = 0; it < 8; it++) {
        int c16 = tid + it * 64;
        int row = c16 >> 3, col = c16 & 7;
        cp_async16(sq + (uint32_t)(row * PITCH + col * 4) * 4, qg + row * 32 + col * 4);
    }
    #pragma unroll
    for (int it = 0; it < 7; it++) {
        int c16 = tid + it * 64;
        int row = c16 >> 3, col = c16 & 7;
        cp_async16(sk + (uint32_t)(row * PITCH + col * 4) * 4, kg + row * 32 + col * 4);
    }
    #pragma unroll
    for (int it = 0; it < 8; it++) {
        int c16 = tid + it * 64;
        int row = c16 >> 4, col = c16 & 15;
        cp_async16(sv + (uint32_t)(row * VP + col * 4) * 4, vg + row * 64 + col * 4);
    }
    CP_COMMIT();

    // ---- prefetch bias+mask (bf16x2) while copies fly ----
    const __nv_bfloat16* bmg = g_bm + ((size_t)((b & (NWIN - 1)) * HEADS + h)) * (64 * 56);
    uint32_t bmr[2][2][7];
    #pragma unroll
    for (int mi = 0; mi < 2; mi++) {
        const int r0 = rbase + mi * 16 + g;
        #pragma unroll
        for (int nj = 0; nj < 7; nj++) {
            const int cc = nj * 8 + 2 * q;
            bmr[mi][0][nj] = *(const uint32_t*)(bmg + r0 * 56 + cc);
            bmr[mi][1][nj] = *(const uint32_t*)(bmg + (r0 + 8) * 56 + cc);
        }
    }

    CP_WAIT0();
    __syncthreads();

    // ---- QK^T ----
    float s[2][7][4];
    #pragma unroll
    for (int mi = 0; mi < 2; mi++)
        #pragma unroll
        for (int nj = 0; nj < 7; nj++)
            #pragma unroll
            for (int r = 0; r < 4; r++) s[mi][nj][r] = 0.0f;

    #pragma unroll
    for (int ks = 0; ks < 4; ks++) {
        const int kc = ks * 8 + q;
        uint32_t b0[7], b1[7];
        #pragma unroll
        for (int nj = 0; nj < 7; nj++) {
            const float* bp = Ks + (nj * 8 + g) * PITCH + kc;
            b0[nj] = __float_as_uint(bp[0]);
            b1[nj] = __float_as_uint(bp[4]);
        }
        #pragma unroll
        for (int mi = 0; mi < 2; mi++) {
            const float* ap = Qs + (rbase + mi * 16 + g) * PITCH + kc;
            uint32_t a0 = __float_as_uint(ap[0]);
            uint32_t a2 = __float_as_uint(ap[4]);
            uint32_t a1 = __float_as_uint(ap[8 * PITCH]);
            uint32_t a3 = __float_as_uint(ap[8 * PITCH + 4]);
            #pragma unroll
            for (int nj = 0; nj < 7; nj++)
                MMA_TF32(s[mi][nj], a0, a1, a2, a3, b0[nj], b1[nj]);
        }
    }

    // ---- softmax ----
    float inv[2][2];
    #pragma unroll
    for (int mi = 0; mi < 2; mi++) {
        float l0 = 0.0f, l1 = 0.0f;
        #pragma unroll
        for (int nj = 0; nj < 7; nj++) {
            float2 bmA = __bfloat1622float2(*(__nv_bfloat162*)&bmr[mi][0][nj]);
            float2 bmB = __bfloat1622float2(*(__nv_bfloat162*)&bmr[mi][1][nj]);
            float e0 = __expf(s[mi][nj][0] + bmA.x);
            float e1 = __expf(s[mi][nj][1] + bmA.y);
            float e2 = __expf(s[mi][nj][2] + bmB.x);
            float e3 = __expf(s[mi][nj][3] + bmB.y);
            s[mi][nj][0] = e0; s[mi][nj][1] = e1;
            s[mi][nj][2] = e2; s[mi][nj][3] = e3;
            l0 += e0 + e1;
            l1 += e2 + e3;
        }
        l0 += __shfl_xor_sync(0xffffffffu, l0, 1);
        l0 += __shfl_xor_sync(0xffffffffu, l0, 2);
        l1 += __shfl_xor_sync(0xffffffffu, l1, 1);
        l1 += __shfl_xor_sync(0xffffffffu, l1, 2);
        inv[mi][0] = 1.0f / l0;
        inv[mi][1] = 1.0f / l1;
    }

    __syncthreads();   // both warps done reading Qs/Ks before P overwrites

    // ---- stage P ----
    #pragma unroll
    for (int mi = 0; mi < 2; mi++) {
        const int r0 = rbase + mi * 16 + g;
        #pragma unroll
        for (int nj = 0; nj < 7; nj++) {
            const int cc = nj * 8 + 2 * q;
            *(float2*)(Ps + r0 * 60 + cc)       = make_float2(s[mi][nj][0], s[mi][nj][1]);
            *(float2*)(Ps + (r0 + 8) * 60 + cc) = make_float2(s[mi][nj][2], s[mi][nj][3]);
        }
    }
    __syncwarp();

    // ---- P x V ----
    float o[2][4][4];
    #pragma unroll
    for (int mi = 0; mi < 2; mi++)
        #pragma unroll
        for (int nj = 0; nj < 4; nj++)
            #pragma unroll
            for (int r = 0; r < 4; r++) o[mi][nj][r] = 0.0f;

    #pragma unroll
    for (int ks = 0; ks < 7; ks++) {
        const int kc = ks * 8 + q;
        uint32_t b0[4], b1[4];
        #pragma unroll
        for (int nj = 0; nj < 4; nj++) {
            const float* bp = Vts + (nj * 8 + g) * VP + kc;
            b0[nj] = __float_as_uint(bp[0]);
            b1[nj] = __float_as_uint(bp[4]);
        }
        #pragma unroll
        for (int mi = 0; mi < 2; mi++) {
            const float* ap = Ps + (rbase + mi * 16 + g) * 60 + kc;
            uint32_t a0 = __float_as_uint(ap[0]);
            uint32_t a2 = __float_as_uint(ap[4]);
            uint32_t a1 = __float_as_uint(ap[8 * 60]);
            uint32_t a3 = __float_as_uint(ap[8 * 60 + 4]);
            #pragma unroll
            for (int nj = 0; nj < 4; nj++)
                MMA_TF32(o[mi][nj], a0, a1, a2, a3, b0[nj], b1[nj]);
        }
    }

    // ---- normalize + store to g_y (tf32-rounded, kperm) ----
    const int p0 = ((q & 1) << 2) | (q >> 1);   // phys col of logical 2q; +2 for 2q+1
    #pragma unroll
    for (int mi = 0; mi < 2; mi++) {
        #pragma unroll
        for (int rr = 0; rr < 2; rr++) {
            const int row = rbase + mi * 16 + g + rr * 8;
            if (row < NTOK) {
                const float iv = inv[mi][rr];
                float* dst = g_y + ((size_t)b * NTOK + row) * CDIM + h * HD;
                #pragma unroll
                for (int nj = 0; nj < 4; nj++) {
                    dst[nj * 8 + p0]     = to_tf32(o[mi][nj][rr * 2 + 0] * iv);
                    dst[nj * 8 + p0 + 2] = to_tf32(o[mi][nj][rr * 2 + 1] * iv);
                }
            }
        }
    }
}

// ---------------------------------------------------------------------------
// Launch
// ---------------------------------------------------------------------------
extern "C" void kernel_launch(void* const* d_in, const int* in_sizes, int n_in,
                              void* d_out, int out_size)
{
    const float* x          = (const float*)d_in[0];
    const float* mask       = (const float*)d_in[1];
    const float* qkv_w      = (const float*)d_in[2];
    const float* qkv_b      = (const float*)d_in[3];
    const float* bias_table = (const float*)d_in[4];
    const float* proj_w     = (const float*)d_in[5];
    const float* proj_b     = (const float*)d_in[6];
    const int*   rel_idx    = (const int*)d_in[7];
    float* out = (float*)d_out;

    cudaFuncSetAttribute(tc_gemm<0>, cudaFuncAttributeMaxDynamicSharedMemorySize, SMTOT_BYTES);
    cudaFuncSetAttribute(tc_gemm<1>, cudaFuncAttributeMaxDynamicSharedMemorySize, SMTOT_BYTES);

    // 0) fused prepass: bm + both weight transposes + round/permute x
    prep_kernel<<<NB_PREP, 256>>>(x, qkv_w, proj_w, bias_table, mask, rel_idx);

    // 1) QKV: g_xr [200704 x 256] x [256 x 768] -> g_q/g_k/g_v (padded/transposed)
    tc_gemm<0><<<dim3(QKV_N / 128, M_TOTAL / 128), 256, SMTOT_BYTES>>>(qkv_b, nullptr);

    // 2) attention -> g_y (tf32-rounded, kperm)
    attn_mma_kernel<<<BATCH * HEADS, 64>>>();

    // 3) proj: g_y x [256 x 256] -> out
    tc_gemm<1><<<dim3(CDIM / 128, M_TOTAL / 128), 256, SMTOT_BYTES>>>(proj_b, out);
}